// round 4
// baseline (speedup 1.0000x reference)
#include <cuda_runtime.h>
#include <math.h>

#define H 768
#define Bb 4
#define Tt 2048
#define BT (Bb*Tt)   // 8192

#define BM 128
#define BN 128
#define BK 16
#define LDW 132      // padded smem row stride (floats)

// ---------------- scratch (device globals; no allocations allowed) ----------
__device__ float g_xn [BT*H];
__device__ float g_U  [BT*H];
__device__ float g_Q  [BT*H];
__device__ float g_K  [BT*H];
__device__ float g_V  [BT*H];
__device__ float g_A  [Bb*Tt*Tt];   // 4 * 2048 * 2048
__device__ float g_MID[BT*H];

// ---------------- f32x2 helpers (sm_103a packed FMA) ------------------------
__device__ __forceinline__ unsigned long long pk2(float v) {
    unsigned long long r;
    asm("mov.b64 %0, {%1, %1};" : "=l"(r) : "f"(v));
    return r;
}
__device__ __forceinline__ void ffma2(unsigned long long& d,
                                      unsigned long long a,
                                      unsigned long long b) {
    asm("fma.rn.f32x2 %0, %1, %2, %0;" : "+l"(d) : "l"(a), "l"(b));
}
__device__ __forceinline__ float2 up2(unsigned long long v) {
    float2 r;
    asm("mov.b64 {%0, %1}, %2;" : "=f"(r.x), "=f"(r.y) : "l"(v));
    return r;
}

// ---------------- LayerNorm --------------------------------------------------
__global__ void ln_kernel(const float* __restrict__ x,
                          const float* __restrict__ gamma,
                          const float* __restrict__ beta,
                          float* __restrict__ out) {
    int row = blockIdx.x;
    const float* xr = x + (size_t)row * H;
    int t = threadIdx.x;
    float v0 = xr[t], v1 = xr[t + 256], v2 = xr[t + 512];
    float s = v0 + v1 + v2;
    float q = v0 * v0 + v1 * v1 + v2 * v2;
    __shared__ float sm[16];
#pragma unroll
    for (int o = 16; o > 0; o >>= 1) {
        s += __shfl_xor_sync(0xffffffffu, s, o);
        q += __shfl_xor_sync(0xffffffffu, q, o);
    }
    if ((t & 31) == 0) { sm[t >> 5] = s; sm[8 + (t >> 5)] = q; }
    __syncthreads();
    if (t < 8) {
        s = sm[t]; q = sm[8 + t];
#pragma unroll
        for (int o = 4; o > 0; o >>= 1) {
            s += __shfl_xor_sync(0xffu, s, o);
            q += __shfl_xor_sync(0xffu, q, o);
        }
        if (t == 0) { sm[0] = s; sm[1] = q; }
    }
    __syncthreads();
    float mu  = sm[0] * (1.0f / (float)H);
    float var = sm[1] * (1.0f / (float)H) - mu * mu;
    float inv = rsqrtf(var + 1e-5f);
    float* o = out + (size_t)row * H;
    o[t]       = (v0 - mu) * inv * gamma[t]       + beta[t];
    o[t + 256] = (v1 - mu) * inv * gamma[t + 256] + beta[t + 256];
    o[t + 512] = (v2 - mu) * inv * gamma[t + 512] + beta[t + 512];
}

// ---------------- GEMM -------------------------------------------------------
// C[M,N] = epi( A[M,K] * op(B) )    op(B) = B^T (NT: B is [N,K]) or B (NN: [K,N])
// EPI 0: silu(acc + bias[n])
// EPI 1: r = max(acc*scale, 0); out = r*r
// EPI 2: out = aux[m,n] * acc
// EPI 3: acc + bias[n]
template <int EPI, bool NTB>
__global__ __launch_bounds__(256, 2)
void gemm_kernel(const float* __restrict__ A, const float* __restrict__ Bm,
                 const float* __restrict__ bias, const float* __restrict__ aux,
                 float* __restrict__ C,
                 int M, int N, int K,
                 long sA, long sB, long sC, float scale) {
    __shared__ float As[BK * LDW];
    __shared__ float Bs[BK * LDW];

    const float* Ab = A + (size_t)blockIdx.z * sA + (size_t)blockIdx.y * BM * K;
    const float* Bblk;
    if (NTB) Bblk = Bm + (size_t)blockIdx.z * sB + (size_t)blockIdx.x * BN * K;
    else     Bblk = Bm + (size_t)blockIdx.z * sB + (size_t)blockIdx.x * BN;

    int t = threadIdx.x;
    // A load map: 128 rows x 4 k-groups of 4; coalesced 64B per row
    int a_row = t >> 2;            // 0..63 (and +64)
    int a_kg  = (t & 3) << 2;      // 0,4,8,12
    const float* ap0 = Ab + (size_t)a_row * K + a_kg;
    const float* ap1 = ap0 + (size_t)64 * K;

    const float *bp0 = nullptr, *bp1 = nullptr;
    int b_sts0 = 0, b_sts1 = 0;
    if (NTB) {
        bp0 = Bblk + (size_t)a_row * K + a_kg;
        bp1 = bp0 + (size_t)64 * K;
    } else {
        int b_k = t >> 5;            // 0..7 (and +8)
        int b_n = (t & 31) << 2;     // 0..124 step 4
        bp0 = Bblk + (size_t)b_k * N + b_n;
        bp1 = bp0 + (size_t)8 * N;
        b_sts0 = b_k * LDW + b_n;
        b_sts1 = (b_k + 8) * LDW + b_n;
    }

    int tx = t & 15, ty = t >> 4;

    unsigned long long acc[8][4];
#pragma unroll
    for (int i = 0; i < 8; i++)
#pragma unroll
        for (int j = 0; j < 4; j++) acc[i][j] = 0ull;

    for (int k0 = 0; k0 < K; k0 += BK) {
        float4 av0 = *(const float4*)(ap0 + k0);
        float4 av1 = *(const float4*)(ap1 + k0);
        float4 bv0, bv1;
        if (NTB) {
            bv0 = *(const float4*)(bp0 + k0);
            bv1 = *(const float4*)(bp1 + k0);
        } else {
            bv0 = *(const float4*)(bp0 + (size_t)k0 * N);
            bv1 = *(const float4*)(bp1 + (size_t)k0 * N);
        }
        __syncthreads();
        As[(a_kg + 0) * LDW + a_row]      = av0.x;
        As[(a_kg + 1) * LDW + a_row]      = av0.y;
        As[(a_kg + 2) * LDW + a_row]      = av0.z;
        As[(a_kg + 3) * LDW + a_row]      = av0.w;
        As[(a_kg + 0) * LDW + a_row + 64] = av1.x;
        As[(a_kg + 1) * LDW + a_row + 64] = av1.y;
        As[(a_kg + 2) * LDW + a_row + 64] = av1.z;
        As[(a_kg + 3) * LDW + a_row + 64] = av1.w;
        if (NTB) {
            Bs[(a_kg + 0) * LDW + a_row]      = bv0.x;
            Bs[(a_kg + 1) * LDW + a_row]      = bv0.y;
            Bs[(a_kg + 2) * LDW + a_row]      = bv0.z;
            Bs[(a_kg + 3) * LDW + a_row]      = bv0.w;
            Bs[(a_kg + 0) * LDW + a_row + 64] = bv1.x;
            Bs[(a_kg + 1) * LDW + a_row + 64] = bv1.y;
            Bs[(a_kg + 2) * LDW + a_row + 64] = bv1.z;
            Bs[(a_kg + 3) * LDW + a_row + 64] = bv1.w;
        } else {
            *(float4*)&Bs[b_sts0] = bv0;
            *(float4*)&Bs[b_sts1] = bv1;
        }
        __syncthreads();
#pragma unroll
        for (int kk = 0; kk < BK; kk++) {
            const float* arow = &As[kk * LDW + ty * 8];
            float4 aA = *(const float4*)arow;
            float4 aB = *(const float4*)(arow + 4);
            const float* brow = &Bs[kk * LDW + tx * 8];
            ulonglong2 b01 = *(const ulonglong2*)brow;
            ulonglong2 b23 = *(const ulonglong2*)(brow + 4);
            float a_s[8] = {aA.x, aA.y, aA.z, aA.w, aB.x, aB.y, aB.z, aB.w};
#pragma unroll
            for (int i = 0; i < 8; i++) {
                unsigned long long a2 = pk2(a_s[i]);
                ffma2(acc[i][0], a2, b01.x);
                ffma2(acc[i][1], a2, b01.y);
                ffma2(acc[i][2], a2, b23.x);
                ffma2(acc[i][3], a2, b23.y);
            }
        }
    }

    // ---------------- epilogue ----------------
    size_t n0 = (size_t)blockIdx.x * BN + tx * 8;
    size_t m0 = (size_t)blockIdx.y * BM + ty * 8;
    float* Crow = C + (size_t)blockIdx.z * sC + m0 * N + n0;
    const float* Xrow = nullptr;
    if (EPI == 2) Xrow = aux + (size_t)blockIdx.z * sC + m0 * N + n0;

    float bvals[8];
    if (EPI == 0 || EPI == 3) {
#pragma unroll
        for (int j = 0; j < 8; j++) bvals[j] = bias[n0 + j];
    }

#pragma unroll
    for (int i = 0; i < 8; i++) {
        float v[8];
#pragma unroll
        for (int j = 0; j < 4; j++) {
            float2 p = up2(acc[i][j]);
            v[2 * j]     = p.x;
            v[2 * j + 1] = p.y;
        }
        if (EPI == 0) {
#pragma unroll
            for (int j = 0; j < 8; j++) {
                float s = v[j] + bvals[j];
                v[j] = s / (1.0f + __expf(-s));
            }
        } else if (EPI == 1) {
#pragma unroll
            for (int j = 0; j < 8; j++) {
                float r = fmaxf(v[j] * scale, 0.0f);
                v[j] = r * r;
            }
        } else if (EPI == 2) {
            float4 u0 = *(const float4*)(Xrow + (size_t)i * N);
            float4 u1 = *(const float4*)(Xrow + (size_t)i * N + 4);
            v[0] *= u0.x; v[1] *= u0.y; v[2] *= u0.z; v[3] *= u0.w;
            v[4] *= u1.x; v[5] *= u1.y; v[6] *= u1.z; v[7] *= u1.w;
        } else {  // EPI == 3
#pragma unroll
            for (int j = 0; j < 8; j++) v[j] += bvals[j];
        }
        *(float4*)(Crow + (size_t)i * N)     = make_float4(v[0], v[1], v[2], v[3]);
        *(float4*)(Crow + (size_t)i * N + 4) = make_float4(v[4], v[5], v[6], v[7]);
    }
}

// ---------------- host launch ------------------------------------------------
extern "C" void kernel_launch(void* const* d_in, const int* in_sizes, int n_in,
                              void* d_out, int out_size) {
    const float* hs = (const float*)d_in[0];
    const float* lg = (const float*)d_in[1];
    const float* lb = (const float*)d_in[2];
    const float* Wu = (const float*)d_in[3];
    const float* bu = (const float*)d_in[4];
    const float* Wq = (const float*)d_in[5];
    const float* bq = (const float*)d_in[6];
    const float* Wk = (const float*)d_in[7];
    const float* bk = (const float*)d_in[8];
    const float* Wv = (const float*)d_in[9];
    const float* bv = (const float*)d_in[10];
    const float* Wo = (const float*)d_in[11];
    const float* bo = (const float*)d_in[12];
    float* out = (float*)d_out;

    float *xn, *U, *Q, *Kp, *V, *Am, *MID;
    cudaGetSymbolAddress((void**)&xn,  g_xn);
    cudaGetSymbolAddress((void**)&U,   g_U);
    cudaGetSymbolAddress((void**)&Q,   g_Q);
    cudaGetSymbolAddress((void**)&Kp,  g_K);
    cudaGetSymbolAddress((void**)&V,   g_V);
    cudaGetSymbolAddress((void**)&Am,  g_A);
    cudaGetSymbolAddress((void**)&MID, g_MID);

    const float scale = 0.022097086912079608f;  // 1/sqrt(2048)

    ln_kernel<<<BT, 256>>>(hs, lg, lb, xn);

    dim3 gp(H / BN, BT / BM, 1);
    gemm_kernel<0, true><<<gp, 256>>>(xn, Wu, bu, nullptr, U,  BT, H, H, 0, 0, 0, 0.f);
    gemm_kernel<0, true><<<gp, 256>>>(xn, Wq, bq, nullptr, Q,  BT, H, H, 0, 0, 0, 0.f);
    gemm_kernel<0, true><<<gp, 256>>>(xn, Wk, bk, nullptr, Kp, BT, H, H, 0, 0, 0, 0.f);
    gemm_kernel<0, true><<<gp, 256>>>(xn, Wv, bv, nullptr, V,  BT, H, H, 0, 0, 0, 0.f);

    dim3 gs(Tt / BN, Tt / BM, Bb);
    gemm_kernel<1, true><<<gs, 256>>>(Q, Kp, nullptr, nullptr, Am, Tt, Tt, H,
                                      (long)Tt * H, (long)Tt * H, (long)Tt * Tt, scale);

    dim3 ga(H / BN, Tt / BM, Bb);
    gemm_kernel<2, false><<<ga, 256>>>(Am, V, nullptr, U, MID, Tt, H, Tt,
                                       (long)Tt * Tt, (long)Tt * H, (long)Tt * H, 0.f);

    dim3 gf(H / BN, BT / BM, 1);
    gemm_kernel<3, true><<<gf, 256>>>(MID, Wo, bo, nullptr, out, BT, H, H, 0, 0, 0, 0.f);
}

// round 6
// speedup vs baseline: 2.6790x; 2.6790x over previous
#include <cuda_runtime.h>
#include <cuda_bf16.h>
#include <math.h>
#include <stdint.h>

#define H 768
#define Bb 4
#define Tt 2048
#define BT (Bb*Tt)          // 8192
#define SMEM_BYTES 65536     // 2 stages * 32KB

// ---------------- device scratch (no allocations allowed) --------------------
__device__ __nv_bfloat16 g_xnh[BT*H], g_xnl[BT*H];
__device__ __nv_bfloat16 g_Qh[BT*H],  g_Ql[BT*H];
__device__ __nv_bfloat16 g_Kh[BT*H],  g_Kl[BT*H];
__device__ __nv_bfloat16 g_Vth[BT*H], g_Vtl[BT*H];   // V^T: [b][d][t]
__device__ float         g_U[BT*H];
__device__ __nv_bfloat16 g_Sh[(size_t)Bb*Tt*Tt], g_Sl[(size_t)Bb*Tt*Tt];
__device__ __nv_bfloat16 g_Mh[BT*H],  g_Ml[BT*H];
__device__ __nv_bfloat16 g_Wh[5*H*H], g_Wl[5*H*H];

// ---------------- PTX helpers ------------------------------------------------
__device__ __forceinline__ uint32_t s2u(const void* p) {
    uint32_t a;
    asm("{ .reg .u64 t; cvta.to.shared.u64 t, %1; cvt.u32.u64 %0, t; }" : "=r"(a) : "l"(p));
    return a;
}
__device__ __forceinline__ void cp16(uint32_t d, const void* s) {
    asm volatile("cp.async.cg.shared.global [%0], [%1], 16;" :: "r"(d), "l"(s));
}
__device__ __forceinline__ void ldmx4(uint32_t* r, uint32_t a) {
    asm volatile("ldmatrix.sync.aligned.m8n8.x4.shared.b16 {%0,%1,%2,%3}, [%4];"
        : "=r"(r[0]), "=r"(r[1]), "=r"(r[2]), "=r"(r[3]) : "r"(a));
}
__device__ __forceinline__ void mma16816(float* c, const uint32_t* a,
                                         uint32_t b0, uint32_t b1) {
    asm volatile("mma.sync.aligned.m16n8k16.row.col.f32.bf16.bf16.f32 "
        "{%0,%1,%2,%3}, {%4,%5,%6,%7}, {%8,%9}, {%0,%1,%2,%3};"
        : "+f"(c[0]), "+f"(c[1]), "+f"(c[2]), "+f"(c[3])
        : "r"(a[0]), "r"(a[1]), "r"(a[2]), "r"(a[3]), "r"(b0), "r"(b1));
}

// ---------------- LayerNorm (fp32 math, bf16 hi/lo output) -------------------
__global__ void ln_kernel(const float* __restrict__ x, const float* __restrict__ gamma,
                          const float* __restrict__ beta,
                          __nv_bfloat16* __restrict__ oh, __nv_bfloat16* __restrict__ ol) {
    int row = blockIdx.x;
    const float* xr = x + (size_t)row * H;
    int t = threadIdx.x;
    float v0 = xr[t], v1 = xr[t + 256], v2 = xr[t + 512];
    float s = v0 + v1 + v2;
    float q = v0 * v0 + v1 * v1 + v2 * v2;
    __shared__ float sm[16];
#pragma unroll
    for (int o = 16; o > 0; o >>= 1) {
        s += __shfl_xor_sync(0xffffffffu, s, o);
        q += __shfl_xor_sync(0xffffffffu, q, o);
    }
    if ((t & 31) == 0) { sm[t >> 5] = s; sm[8 + (t >> 5)] = q; }
    __syncthreads();
    if (t < 8) {
        s = sm[t]; q = sm[8 + t];
#pragma unroll
        for (int o = 4; o > 0; o >>= 1) {
            s += __shfl_xor_sync(0xffu, s, o);
            q += __shfl_xor_sync(0xffu, q, o);
        }
        if (t == 0) { sm[0] = s; sm[1] = q; }
    }
    __syncthreads();
    float mu  = sm[0] * (1.0f / (float)H);
    float var = sm[1] * (1.0f / (float)H) - mu * mu;
    float inv = rsqrtf(var + 1e-5f);
    size_t base = (size_t)row * H;
#pragma unroll
    for (int e = 0; e < 3; e++) {
        int c = t + e * 256;
        float v = (e == 0) ? v0 : (e == 1) ? v1 : v2;
        float y = (v - mu) * inv * gamma[c] + beta[c];
        __nv_bfloat16 hh = __float2bfloat16(y);
        oh[base + c] = hh;
        ol[base + c] = __float2bfloat16(y - __bfloat162float(hh));
    }
}

// ---------------- fp32 -> bf16 hi/lo -----------------------------------------
__global__ void cvt_kernel(const float* __restrict__ x, __nv_bfloat16* __restrict__ h,
                           __nv_bfloat16* __restrict__ l, int n) {
    int i = blockIdx.x * 256 + threadIdx.x;
    if (i < n) {
        float v = x[i];
        __nv_bfloat16 hh = __float2bfloat16(v);
        h[i] = hh;
        l[i] = __float2bfloat16(v - __bfloat162float(hh));
    }
}

// ---------------- HMMA (mma.sync) GEMM ---------------------------------------
// C[M,N] = epi( A[M,K] * B[N,K]^T ), bf16 hi/lo operands, 3-pass fp32 accum.
// Tiles: CTA 128x128x32, warp 32x64, mma m16n8k16.
// EPI 0: silu(acc+bias[n])  1: (max(acc*scale,0))^2  2: aux[m,n]*acc
// EPI 3: acc+bias[n]        4: silu(acc+bias[m])
// OUTM 0: fp32 to Cf        1: hi/lo bf16 to Ch/Cl   2: hi/lo with V^T addressing
template<int EPI, int OUTM>
__global__ void __launch_bounds__(256)
hmma_gemm(const __nv_bfloat16* __restrict__ Ah, const __nv_bfloat16* __restrict__ Al,
          const __nv_bfloat16* __restrict__ Bh, const __nv_bfloat16* __restrict__ Bl,
          const float* __restrict__ bias, const float* __restrict__ aux,
          float* __restrict__ Cf, __nv_bfloat16* __restrict__ Ch, __nv_bfloat16* __restrict__ Cl,
          int K, int ldC, long sA, long sB, long sC, float scale)
{
    extern __shared__ __align__(1024) char smem[];
    const uint32_t sb = s2u(smem);
    const int tid  = threadIdx.x;
    const int lane = tid & 31;
    const int wid  = tid >> 5;
    const int wm   = (wid & 3) * 32;    // warp M offset
    const int wn   = (wid >> 2) * 64;   // warp N offset
    const int m0 = blockIdx.y * 128;
    const int n0 = blockIdx.x * 128;
    const int bz = blockIdx.z;

    const __nv_bfloat16* gop[4];
    gop[0] = Ah + (size_t)bz * sA + (size_t)m0 * K;
    gop[1] = Al + (size_t)bz * sA + (size_t)m0 * K;
    gop[2] = Bh + (size_t)bz * sB + (size_t)n0 * K;
    gop[3] = Bl + (size_t)bz * sB + (size_t)n0 * K;

    // producer map: per op-tile, 512 16B chunks (128 rows x 4), 2 per thread
    const int pr0 = tid >> 2;              // rows tid>>2 and +64
    const int pch = tid & 3;
    const uint32_t pso0 = (uint32_t)(pr0 * 64 + pch * 16) ^ ((((uint32_t)pr0 >> 1) & 3) << 4);
    const int pr1 = pr0 + 64;
    const uint32_t pso1 = (uint32_t)(pr1 * 64 + pch * 16) ^ ((((uint32_t)pr1 >> 1) & 3) << 4);

    // ldmatrix lane addressing (xor constant per lane; row bits 1-2 fixed mod 16)
    const int rA  = lane & 15;
    const uint32_t chA  = ((lane >> 4) & 1) * 16;
    const uint32_t xorA = (((uint32_t)rA >> 1) & 3) << 4;
    const uint32_t aOff = (uint32_t)((wm + rA) * 64) + chA;
    const int rB  = (lane & 7) | (((lane >> 4) & 1) << 3);
    const uint32_t chB  = ((lane >> 3) & 1) * 16;
    const uint32_t xorB = (((uint32_t)rB >> 1) & 3) << 4;
    const uint32_t bOff = (uint32_t)((wn + rB) * 64) + chB;

    float acc[2][8][4];
#pragma unroll
    for (int a = 0; a < 2; a++)
#pragma unroll
        for (int b = 0; b < 8; b++)
#pragma unroll
            for (int c = 0; c < 4; c++) acc[a][b][c] = 0.f;

#define LOAD_STAGE(SBASE, K0) do {                                            \
    _Pragma("unroll")                                                         \
    for (int op = 0; op < 4; op++) {                                          \
        const __nv_bfloat16* g = gop[op];                                     \
        cp16(sb + (SBASE) + op * 8192 + pso0,                                 \
             g + (size_t)pr0 * K + (K0) + pch * 8);                           \
        cp16(sb + (SBASE) + op * 8192 + pso1,                                 \
             g + (size_t)pr1 * K + (K0) + pch * 8);                           \
    }                                                                         \
    asm volatile("cp.async.commit_group;" ::: "memory");                      \
} while (0)

    const int nch = K >> 5;
    LOAD_STAGE(0u, 0);

    for (int i = 0; i < nch; i++) {
        if (i + 1 < nch) {
            LOAD_STAGE((uint32_t)(((i + 1) & 1) * 32768), (i + 1) * 32);
            asm volatile("cp.async.wait_group 1;" ::: "memory");
        } else {
            asm volatile("cp.async.wait_group 0;" ::: "memory");
        }
        __syncthreads();

        const uint32_t st = sb + (uint32_t)((i & 1) * 32768);
#pragma unroll
        for (int ks = 0; ks < 2; ks++) {
            uint32_t ah[2][4], al[2][4];
#pragma unroll
            for (int mt = 0; mt < 2; mt++) {
                uint32_t base = st + aOff + (uint32_t)(mt * 1024 + ks * 32);
                ldmx4(ah[mt], base ^ xorA);
                ldmx4(al[mt], (base + 8192u) ^ xorA);
            }
#pragma unroll
            for (int ng = 0; ng < 4; ng++) {
                uint32_t bh[4], bl[4];
                uint32_t base = st + 16384u + bOff + (uint32_t)(ng * 1024 + ks * 32);
                ldmx4(bh, base ^ xorB);
                ldmx4(bl, (base + 8192u) ^ xorB);
#pragma unroll
                for (int mt = 0; mt < 2; mt++) {
#pragma unroll
                    for (int hf = 0; hf < 2; hf++) {
                        float* c = acc[mt][ng * 2 + hf];
                        mma16816(c, ah[mt], bh[2 * hf], bh[2 * hf + 1]);
                        mma16816(c, ah[mt], bl[2 * hf], bl[2 * hf + 1]);
                        mma16816(c, al[mt], bh[2 * hf], bh[2 * hf + 1]);
                    }
                }
            }
        }
        __syncthreads();
    }
#undef LOAD_STAGE

    // ---------------- epilogue ----------------
    const int mB = m0 + wm + (lane >> 2);
    const int nB = n0 + wn + (lane & 3) * 2;

#pragma unroll
    for (int mt = 0; mt < 2; mt++) {
#pragma unroll
        for (int nt = 0; nt < 8; nt++) {
#pragma unroll
            for (int h = 0; h < 2; h++) {
                int m = mB + mt * 16 + h * 8;
                int n = nB + nt * 8;
                float x0 = acc[mt][nt][2 * h];
                float x1 = acc[mt][nt][2 * h + 1];

                if (EPI == 0 || EPI == 3) {
                    float2 b2 = *(const float2*)(bias + n);
                    x0 += b2.x; x1 += b2.y;
                    if (EPI == 0) {
                        x0 = x0 / (1.0f + __expf(-x0));
                        x1 = x1 / (1.0f + __expf(-x1));
                    }
                } else if (EPI == 4) {
                    float rb = bias[m];
                    x0 += rb; x1 += rb;
                    x0 = x0 / (1.0f + __expf(-x0));
                    x1 = x1 / (1.0f + __expf(-x1));
                } else if (EPI == 1) {
                    float r0 = fmaxf(x0 * scale, 0.0f);
                    float r1 = fmaxf(x1 * scale, 0.0f);
                    x0 = r0 * r0; x1 = r1 * r1;
                } else if (EPI == 2) {
                    float2 a2 = *(const float2*)(aux + (size_t)bz * sC + (size_t)m * ldC + n);
                    x0 *= a2.x; x1 *= a2.y;
                }

                if (OUTM == 0) {
                    *(float2*)(Cf + (size_t)bz * sC + (size_t)m * ldC + n) =
                        make_float2(x0, x1);
                } else {
                    size_t base;
                    if (OUTM == 1) base = (size_t)bz * sC + (size_t)m * ldC + n;
                    else {
                        int bidx = n >> 11, t = n & 2047;
                        base = (size_t)bidx * ((size_t)H * Tt) + (size_t)m * Tt + t;
                    }
                    __nv_bfloat16 h0 = __float2bfloat16(x0);
                    __nv_bfloat16 h1 = __float2bfloat16(x1);
                    __nv_bfloat162 hh; hh.x = h0; hh.y = h1;
                    __nv_bfloat162 ll;
                    ll.x = __float2bfloat16(x0 - __bfloat162float(h0));
                    ll.y = __float2bfloat16(x1 - __bfloat162float(h1));
                    *(__nv_bfloat162*)(Ch + base) = hh;
                    *(__nv_bfloat162*)(Cl + base) = ll;
                }
            }
        }
    }
}

// ---------------- host launch ------------------------------------------------
extern "C" void kernel_launch(void* const* d_in, const int* in_sizes, int n_in,
                              void* d_out, int out_size) {
    const float* hs = (const float*)d_in[0];
    const float* lg = (const float*)d_in[1];
    const float* lb = (const float*)d_in[2];
    const float* Wu = (const float*)d_in[3];
    const float* bu = (const float*)d_in[4];
    const float* Wq = (const float*)d_in[5];
    const float* bq = (const float*)d_in[6];
    const float* Wk = (const float*)d_in[7];
    const float* bk = (const float*)d_in[8];
    const float* Wv = (const float*)d_in[9];
    const float* bv = (const float*)d_in[10];
    const float* Wo = (const float*)d_in[11];
    const float* bo = (const float*)d_in[12];
    float* out = (float*)d_out;

    __nv_bfloat16 *xnh, *xnl, *Qh, *Ql, *Kh, *Kl, *Vth, *Vtl, *Sh, *Sl, *Mh, *Ml, *Wh, *Wl;
    float* U;
    cudaGetSymbolAddress((void**)&xnh, g_xnh); cudaGetSymbolAddress((void**)&xnl, g_xnl);
    cudaGetSymbolAddress((void**)&Qh,  g_Qh);  cudaGetSymbolAddress((void**)&Ql,  g_Ql);
    cudaGetSymbolAddress((void**)&Kh,  g_Kh);  cudaGetSymbolAddress((void**)&Kl,  g_Kl);
    cudaGetSymbolAddress((void**)&Vth, g_Vth); cudaGetSymbolAddress((void**)&Vtl, g_Vtl);
    cudaGetSymbolAddress((void**)&Sh,  g_Sh);  cudaGetSymbolAddress((void**)&Sl,  g_Sl);
    cudaGetSymbolAddress((void**)&Mh,  g_Mh);  cudaGetSymbolAddress((void**)&Ml,  g_Ml);
    cudaGetSymbolAddress((void**)&Wh,  g_Wh);  cudaGetSymbolAddress((void**)&Wl,  g_Wl);
    cudaGetSymbolAddress((void**)&U,   g_U);

    cudaFuncSetAttribute(hmma_gemm<0,0>, cudaFuncAttributeMaxDynamicSharedMemorySize, SMEM_BYTES);
    cudaFuncSetAttribute(hmma_gemm<0,1>, cudaFuncAttributeMaxDynamicSharedMemorySize, SMEM_BYTES);
    cudaFuncSetAttribute(hmma_gemm<4,2>, cudaFuncAttributeMaxDynamicSharedMemorySize, SMEM_BYTES);
    cudaFuncSetAttribute(hmma_gemm<1,1>, cudaFuncAttributeMaxDynamicSharedMemorySize, SMEM_BYTES);
    cudaFuncSetAttribute(hmma_gemm<2,1>, cudaFuncAttributeMaxDynamicSharedMemorySize, SMEM_BYTES);
    cudaFuncSetAttribute(hmma_gemm<3,0>, cudaFuncAttributeMaxDynamicSharedMemorySize, SMEM_BYTES);

    const float scale = 0.022097086912079608f;  // 1/sqrt(2048)
    const int NW = H * H;
    const int cvtg = (NW + 255) / 256;

    cvt_kernel<<<cvtg, 256>>>(Wu, Wh + 0*NW, Wl + 0*NW, NW);
    cvt_kernel<<<cvtg, 256>>>(Wq, Wh + 1*NW, Wl + 1*NW, NW);
    cvt_kernel<<<cvtg, 256>>>(Wk, Wh + 2*NW, Wl + 2*NW, NW);
    cvt_kernel<<<cvtg, 256>>>(Wv, Wh + 3*NW, Wl + 3*NW, NW);
    cvt_kernel<<<cvtg, 256>>>(Wo, Wh + 4*NW, Wl + 4*NW, NW);

    ln_kernel<<<BT, 256>>>(hs, lg, lb, xnh, xnl);

    // projections: M=8192, N=768, K=768 (NT)
    dim3 gp(H / 128, BT / 128, 1);
    hmma_gemm<0,0><<<gp, 256, SMEM_BYTES>>>(xnh, xnl, Wh + 0*NW, Wl + 0*NW, bu, nullptr,
                                            U, nullptr, nullptr, H, H, 0, 0, 0, 0.f);
    hmma_gemm<0,1><<<gp, 256, SMEM_BYTES>>>(xnh, xnl, Wh + 1*NW, Wl + 1*NW, bq, nullptr,
                                            nullptr, Qh, Ql, H, H, 0, 0, 0, 0.f);
    hmma_gemm<0,1><<<gp, 256, SMEM_BYTES>>>(xnh, xnl, Wh + 2*NW, Wl + 2*NW, bk, nullptr,
                                            nullptr, Kh, Kl, H, H, 0, 0, 0, 0.f);
    // V^T = Wv @ xn^T: M=768, N=8192, K=768; silu + row bias; V^T addressing
    dim3 gv(BT / 128, H / 128, 1);
    hmma_gemm<4,2><<<gv, 256, SMEM_BYTES>>>(Wh + 3*NW, Wl + 3*NW, xnh, xnl, bv, nullptr,
                                            nullptr, Vth, Vtl, H, 0, 0, 0, 0, 0.f);
    // S = relu(QK^T * scale)^2: per batch M=N=2048, K=768
    dim3 gs(Tt / 128, Tt / 128, Bb);
    hmma_gemm<1,1><<<gs, 256, SMEM_BYTES>>>(Qh, Ql, Kh, Kl, nullptr, nullptr,
                                            nullptr, Sh, Sl, H, Tt,
                                            (long)Tt * H, (long)Tt * H, (long)Tt * Tt, scale);
    // MID = U .* (S @ V): per batch M=2048, N=768, K=2048 (B = V^T rows, K-major)
    dim3 ga(H / 128, Tt / 128, Bb);
    hmma_gemm<2,1><<<ga, 256, SMEM_BYTES>>>(Sh, Sl, Vth, Vtl, nullptr, U,
                                            nullptr, Mh, Ml, Tt, H,
                                            (long)Tt * Tt, (long)H * Tt, (long)Tt * H, 0.f);
    // out = MID @ Wo^T + bo: M=8192, N=768, K=768
    hmma_gemm<3,0><<<gp, 256, SMEM_BYTES>>>(Mh, Ml, Wh + 4*NW, Wl + 4*NW, bo, nullptr,
                                            out, nullptr, nullptr, H, H, 0, 0, 0, 0.f);
}